// round 16
// baseline (speedup 1.0000x reference)
#include <cuda_runtime.h>

#define B_SZ 256
#define T_SZ 2000
#define F_SZ 128

#define T_MAIN  1728               // 27*64, streamed in-block
#define T_TAIL  (T_SZ - T_MAIN)    // 272, streamed by helper blocks
#define CHUNK   64
#define NCHUNK  (T_MAIN / CHUNK)   // 27 exact
#define NBUF    8
#define DOT_WARPS 8
#define T_PER_WARP 8
#define THREADS 288                // 9 warps

#define HELP_BLOCKS 40
#define NUNIT_ROW  (T_TAIL / 8)    // 34 slices of 8 ts per row

// BETA = sigmoid(2.0), VTH = 1.0
#define BETA_F 0.8807970779778823f

// tail scratch (zero-init device globals; flags reset by consumer each run)
__device__ float g_cur2[B_SZ * T_TAIL];
__device__ int   g_row_done[B_SZ];

#define BAR_FULL(i)  ((i) & 7)
#define BAR_EMPTY(i) (8 + ((i) & 7))

__device__ __forceinline__ void bar_sync(int id) {
    asm volatile("bar.sync %0, %1;" :: "r"(id), "n"(THREADS) : "memory");
}
__device__ __forceinline__ void bar_arrive(int id) {
    asm volatile("bar.arrive %0, %1;" :: "r"(id), "n"(THREADS) : "memory");
}
static __device__ __forceinline__ int ld_acquire(const int* p) {
    int v;
    asm volatile("ld.acquire.gpu.global.s32 %0, [%1];"
                 : "=r"(v) : "l"(p) : "memory");
    return v;
}
static __device__ __forceinline__ void red_release_add(int* p, int v) {
    asm volatile("red.release.gpu.global.add.s32 [%0], %1;"
                 :: "l"(p), "r"(v) : "memory");
}

__device__ __forceinline__ float lif_step(float& v, float c) {
    float u = fmaf(BETA_F, v, c);
    float w = u - 1.0f;
    bool  p = (u >= 1.0f);
    v = p ? w : u;
    return p ? 1.0f : 0.0f;
}

__global__ void __launch_bounds__(THREADS, 2) lif_fused_kernel(
    const float* __restrict__ x, const float* __restrict__ W,
    const float* __restrict__ bias, float* __restrict__ out, int out_size)
{
    __shared__ float cur_s[NBUF][CHUNK];

    const int wid  = threadIdx.x >> 5;
    const int lane = threadIdx.x & 31;
    const int sub  = lane & 7;
    const int grp  = lane >> 3;

    if (blockIdx.x >= B_SZ) {
        // ============ helper blocks: stream row tails (no hot-loop sync) ====
        const int h = blockIdx.x - B_SZ;
        const int r0 = (h < 16) ? h * 7 : 112 + (h - 16) * 6;
        const int nr = (h < 16) ? 7 : 6;

        float4 w4[4];
        #pragma unroll
        for (int j = 0; j < 4; ++j)
            w4[j] = reinterpret_cast<const float4*>(W)[sub + 8 * j];
        const float bias_v = bias[0];

        for (int r = r0; r < r0 + nr; ++r) {
            const float4* X4 = reinterpret_cast<const float4*>(
                x + (size_t)r * T_SZ * F_SZ);
            float* crow = &g_cur2[r * T_TAIL];

            for (int u = wid; u < NUNIT_ROW; u += 9) {
                const int t0 = T_MAIN + u * 8;
                const float4* xp = X4 + (size_t)t0 * (F_SZ / 4);

                // batch all 8 LDG.128 (4KB in flight), pure streaming
                float4 xv[2][4];
                #pragma unroll
                for (int p = 0; p < 2; ++p)
                    #pragma unroll
                    for (int j = 0; j < 4; ++j)
                        xv[p][j] = __ldcs(xp + (p * 4 + grp) * (F_SZ / 4)
                                             + sub + 8 * j);

                #pragma unroll
                for (int p = 0; p < 2; ++p) {
                    float s = 0.0f;
                    #pragma unroll
                    for (int j = 0; j < 4; ++j) {
                        s = fmaf(xv[p][j].x, w4[j].x, s);
                        s = fmaf(xv[p][j].y, w4[j].y, s);
                        s = fmaf(xv[p][j].z, w4[j].z, s);
                        s = fmaf(xv[p][j].w, w4[j].w, s);
                    }
                    s += __shfl_xor_sync(0xFFFFFFFFu, s, 4);
                    s += __shfl_xor_sync(0xFFFFFFFFu, s, 2);
                    s += __shfl_xor_sync(0xFFFFFFFFu, s, 1);
                    if (sub == 0)
                        crow[u * 8 + p * 4 + grp] = s + bias_v;
                }
            }

            __syncthreads();                 // whole row tail written
            if (threadIdx.x == 0)
                red_release_add(&g_row_done[r], 1);   // ONE release per row
        }
        return;
    }

    // ===================== fused blocks (one row each) =====================
    const int b = blockIdx.x;

    if (wid > 0) {
        // ---------- producers: dot warps 1..8 (R15 style, T_MAIN only) -----
        float4 w4[4];
        #pragma unroll
        for (int j = 0; j < 4; ++j)
            w4[j] = reinterpret_cast<const float4*>(W)[sub + 8 * j];
        const float bias_v = bias[0];

        const int slice0 = (wid - 1) * T_PER_WARP;
        const float4* X4 = reinterpret_cast<const float4*>(
            x + (size_t)b * T_SZ * F_SZ);

        #pragma unroll 1
        for (int c = 0; c < NCHUNK; ++c) {
            const int buf = c & (NBUF - 1);
            const int t0  = c * CHUNK + slice0;

            // Phase 1: batch ALL 8 LDG.128 (regs only, before ring wait)
            float4 xv[2][4];
            #pragma unroll
            for (int p = 0; p < 2; ++p) {
                const float4* rp = X4 + (size_t)(t0 + p * 4 + grp) * (F_SZ / 4)
                                      + sub;
                #pragma unroll
                for (int j = 0; j < 4; ++j)
                    xv[p][j] = __ldcs(rp + 8 * j);
            }

            bar_sync(BAR_EMPTY(c));

            // Phase 2: dot + 3-stage 8-lane butterfly
            #pragma unroll
            for (int p = 0; p < 2; ++p) {
                float s = 0.0f;
                #pragma unroll
                for (int j = 0; j < 4; ++j) {
                    s = fmaf(xv[p][j].x, w4[j].x, s);
                    s = fmaf(xv[p][j].y, w4[j].y, s);
                    s = fmaf(xv[p][j].z, w4[j].z, s);
                    s = fmaf(xv[p][j].w, w4[j].w, s);
                }
                s += __shfl_xor_sync(0xFFFFFFFFu, s, 4);
                s += __shfl_xor_sync(0xFFFFFFFFu, s, 2);
                s += __shfl_xor_sync(0xFFFFFFFFu, s, 1);
                if (sub == 0)
                    cur_s[buf][slice0 + p * 4 + grp - 0] = s + bias_v;
            }

            bar_arrive(BAR_FULL(c));
        }
    } else {
        // ---------- consumer: scan warp 0 ----------
        #pragma unroll
        for (int i = 0; i < NBUF; ++i)
            bar_arrive(BAR_EMPTY(i));

        float v = 0.0f;
        float* out_row = out + (size_t)b * T_SZ;

        // main region: 27 chunks from smem ring
        for (int c = 0; c < NCHUNK; ++c) {
            bar_sync(BAR_FULL(c));

            if (lane == 0) {
                const int buf = c & (NBUF - 1);
                const float4* cs = reinterpret_cast<const float4*>(&cur_s[buf][0]);
                float4* op = reinterpret_cast<float4*>(out_row + c * CHUNK);

                float4 cu = cs[0];
                #pragma unroll 4
                for (int g = 0; g < CHUNK / 4; ++g) {
                    float4 nxt = cu;
                    if (g + 1 < CHUNK / 4) nxt = cs[g + 1];
                    float s0 = lif_step(v, cu.x);
                    float s1 = lif_step(v, cu.y);
                    float s2 = lif_step(v, cu.z);
                    float s3 = lif_step(v, cu.w);
                    op[g] = make_float4(s0, s1, s2, s3);
                    cu = nxt;
                }
            }
            bar_arrive(BAR_EMPTY(c));
        }

        // tail region: 272 steps from helper-produced global buffer
        if (lane == 0) {
            while (ld_acquire(&g_row_done[b]) < 1) { }   // row tail ready

            const float4* c2p = reinterpret_cast<const float4*>(
                &g_cur2[b * T_TAIL]);
            float4* op = reinterpret_cast<float4*>(out_row + T_MAIN);

            float4 a0 = c2p[0], a1 = c2p[1], a2 = c2p[2], a3 = c2p[3];
            #pragma unroll 1
            for (int c = 0; c < T_TAIL / 16; ++c) {
                float4 n0, n1, n2, n3;
                if (c + 1 < T_TAIL / 16) {
                    n0 = c2p[4 * c + 4]; n1 = c2p[4 * c + 5];
                    n2 = c2p[4 * c + 6]; n3 = c2p[4 * c + 7];
                }
                op[4 * c + 0] = make_float4(lif_step(v, a0.x), lif_step(v, a0.y),
                                            lif_step(v, a0.z), lif_step(v, a0.w));
                op[4 * c + 1] = make_float4(lif_step(v, a1.x), lif_step(v, a1.y),
                                            lif_step(v, a1.z), lif_step(v, a1.w));
                op[4 * c + 2] = make_float4(lif_step(v, a2.x), lif_step(v, a2.y),
                                            lif_step(v, a2.z), lif_step(v, a2.w));
                op[4 * c + 3] = make_float4(lif_step(v, a3.x), lif_step(v, a3.y),
                                            lif_step(v, a3.z), lif_step(v, a3.w));
                a0 = n0; a1 = n1; a2 = n2; a3 = n3;
            }

            g_row_done[b] = 0;          // reset for next graph replay
            if (out_size > B_SZ * T_SZ)
                out[B_SZ * T_SZ + b] = v;
        }
    }
}

extern "C" void kernel_launch(void* const* d_in, const int* in_sizes, int n_in,
                              void* d_out, int out_size)
{
    const float* x    = (const float*)d_in[0];  // [256, 2000, 128] fp32
    const float* W    = (const float*)d_in[1];  // [128, 1] fp32
    const float* bias = (const float*)d_in[2];  // [1] fp32
    float* out = (float*)d_out;                 // spikes [256*2000] then vT [256]

    lif_fused_kernel<<<B_SZ + HELP_BLOCKS, THREADS>>>(x, W, bias, out, out_size);
}

// round 17
// speedup vs baseline: 1.1389x; 1.1389x over previous
#include <cuda_runtime.h>

#define B_SZ 256
#define T_SZ 2000
#define F_SZ 128

#define CHUNK   128                // timesteps per chunk
#define NCHUNK  16                 // 16*128 = 2048 >= 2000; last chunk 80 valid
#define DOT_WARPS 8
#define T_PER_WARP 16              // rows per dot warp per chunk
#define NPASS   4                  // 4 rows per pass (8 lanes/row)
#define THREADS (32 * (DOT_WARPS + 1))  // 288

// BETA = sigmoid(2.0), VTH = 1.0
#define BETA_F 0.8807970779778823f

// One physical barrier per chunk (ids 0..15), each used exactly ONCE:
// producers arrive (non-blocking), consumer syncs. No ring, no EMPTY waits,
// no reuse, no phase hazards. __syncthreads() is never used.
__device__ __forceinline__ void bar_sync(int id) {
    asm volatile("bar.sync %0, %1;" :: "r"(id), "n"(THREADS) : "memory");
}
__device__ __forceinline__ void bar_arrive(int id) {
    asm volatile("bar.arrive %0, %1;" :: "r"(id), "n"(THREADS) : "memory");
}

__device__ __forceinline__ float lif_step(float& v, float c) {
    float u = fmaf(BETA_F, v, c);
    float w = u - 1.0f;
    bool  p = (u >= 1.0f);
    v = p ? w : u;
    return p ? 1.0f : 0.0f;
}

__global__ void __launch_bounds__(THREADS, 2) lif_fused_kernel(
    const float* __restrict__ x, const float* __restrict__ W,
    const float* __restrict__ bias, float* __restrict__ out, int out_size)
{
    // whole row's cur fits in smem: 16 chunks x 128 floats = 8KB
    __shared__ float cur_s[NCHUNK * CHUNK];

    const int b    = blockIdx.x;          // batch row
    const int wid  = threadIdx.x >> 5;
    const int lane = threadIdx.x & 31;

    if (wid > 0) {
        // ============ producers: dot warps 1..8 — NEVER block ============
        const int sub = lane & 7;   // position within row (8 lanes x 16 floats)
        const int grp = lane >> 3;  // row within each 4-row pass

        float4 w4[4];
        #pragma unroll
        for (int j = 0; j < 4; ++j)
            w4[j] = reinterpret_cast<const float4*>(W)[sub + 8 * j];
        const float bias_v = bias[0];

        const int slice0 = (wid - 1) * T_PER_WARP;
        const float4* X4 = reinterpret_cast<const float4*>(
            x + (size_t)b * T_SZ * F_SZ);

        #pragma unroll 1
        for (int c = 0; c < NCHUNK; ++c) {
            const int t0 = c * CHUNK + slice0;

            // Phase 1: batch ALL 16 LDG.128 (8KB in flight per warp)
            float4 xv[NPASS][4];
            #pragma unroll
            for (int p = 0; p < NPASS; ++p) {
                int trow = t0 + p * 4 + grp;
                trow = (trow < T_SZ) ? trow : (T_SZ - 1);   // clamp tail
                const float4* rp = X4 + (size_t)trow * (F_SZ / 4) + sub;
                #pragma unroll
                for (int j = 0; j < 4; ++j)
                    xv[p][j] = __ldcs(rp + 8 * j);
            }

            // Phase 2: dot + 3-stage 8-lane butterfly per pass
            #pragma unroll
            for (int p = 0; p < NPASS; ++p) {
                float s = 0.0f;
                #pragma unroll
                for (int j = 0; j < 4; ++j) {
                    s = fmaf(xv[p][j].x, w4[j].x, s);
                    s = fmaf(xv[p][j].y, w4[j].y, s);
                    s = fmaf(xv[p][j].z, w4[j].z, s);
                    s = fmaf(xv[p][j].w, w4[j].w, s);
                }
                s += __shfl_xor_sync(0xFFFFFFFFu, s, 4);
                s += __shfl_xor_sync(0xFFFFFFFFu, s, 2);
                s += __shfl_xor_sync(0xFFFFFFFFu, s, 1);
                const int trow = t0 + p * 4 + grp;
                if (sub == 0 && trow < T_SZ)
                    cur_s[c * CHUNK + (trow - c * CHUNK)] = s + bias_v;
            }

            bar_arrive(c);          // one-shot signal; continue immediately
        }
    } else {
        // ================= consumer: scan warp 0 =================
        float v = 0.0f;
        float* out_row = out + (size_t)b * T_SZ;

        for (int c = 0; c < NCHUNK; ++c) {
            bar_sync(c);            // all 8 producer warps delivered chunk c

            if (lane == 0) {
                const int tbase = c * CHUNK;
                const int ngrp  = ((c == NCHUNK - 1) ? (T_SZ - tbase) : CHUNK) / 4;
                const float4* cs = reinterpret_cast<const float4*>(
                    &cur_s[c * CHUNK]);
                float4* op = reinterpret_cast<float4*>(out_row + tbase);

                float4 cu = cs[0];                      // prefetch group 0
                #pragma unroll 4
                for (int g = 0; g < ngrp; ++g) {
                    float4 nxt = cu;
                    if (g + 1 < ngrp) nxt = cs[g + 1];  // prefetch next group
                    float s0 = lif_step(v, cu.x);
                    float s1 = lif_step(v, cu.y);
                    float s2 = lif_step(v, cu.z);
                    float s3 = lif_step(v, cu.w);
                    op[g] = make_float4(s0, s1, s2, s3);
                    cu = nxt;
                }
            }
        }

        // final membrane potential vT
        if (lane == 0 && out_size > B_SZ * T_SZ)
            out[B_SZ * T_SZ + b] = v;
    }
}

extern "C" void kernel_launch(void* const* d_in, const int* in_sizes, int n_in,
                              void* d_out, int out_size)
{
    const float* x    = (const float*)d_in[0];  // [256, 2000, 128] fp32
    const float* W    = (const float*)d_in[1];  // [128, 1] fp32
    const float* bias = (const float*)d_in[2];  // [1] fp32
    float* out = (float*)d_out;                 // spikes [256*2000] then vT [256]

    lif_fused_kernel<<<B_SZ, THREADS>>>(x, W, bias, out, out_size);
}